// round 8
// baseline (speedup 1.0000x reference)
#include <cuda_runtime.h>
#include <cuda_fp16.h>
#include <cstdint>

#define SS 2048
#define DD 64
#define NBH 32
#define QT 64
#define KCH 64
#define NCH (SS/KCH)                    // 32
#define C_EXP 0.18033688011112042f      // 0.125 * log2(e)

#define CTX_ELEMS (2LL*16*2048*64)
#define PROB_ELEMS (2LL*16*2048*2048)

// ---------------- device-global scratch (allowed) -----------------------------
__device__ __half g_kh[NBH*SS*DD];
__device__ __half g_kl[NBH*SS*DD];
__device__ __half g_vh[NBH*SS*DD];

__global__ void prep_split_kernel(const float* __restrict__ K,
                                  const float* __restrict__ V)
{
    int i = blockIdx.x * 256 + threadIdx.x;
    float k = K[i];
    __half kh = __float2half_rn(k);
    g_kh[i] = kh;
    g_kl[i] = __float2half_rn(k - __half2float(kh));
    g_vh[i] = __float2half_rn(V[i]);
}

// ---------------- smem layout (bytes) ----------------------------------------
// buffer: kh | kl | vh, each 64 rows x 72 half (144B stride) = 9216
#define ARR_B   9216
#define OFF_BUF0 0
#define OFF_BUF1 27648
#define OFF_Q    55296                  // qhi 9216 | qlo 9216
#define OFF_MASK 73728                  // 2048
#define OFF_RSUM 75776                  // 64 floats
#define OFF_RINV 76032                  // 64 floats
#define SMEM_BYTES 76288

__device__ __forceinline__ uint32_t sptr(const void* p) {
    return (uint32_t)__cvta_generic_to_shared(p);
}
__device__ __forceinline__ void ldmA(uint32_t* a, uint32_t addr) {
    asm volatile("ldmatrix.sync.aligned.m8n8.x4.shared.b16 {%0,%1,%2,%3}, [%4];"
                 : "=r"(a[0]), "=r"(a[1]), "=r"(a[2]), "=r"(a[3]) : "r"(addr));
}
__device__ __forceinline__ void ldmB(uint32_t* b, uint32_t addr) {
    asm volatile("ldmatrix.sync.aligned.m8n8.x2.shared.b16 {%0,%1}, [%2];"
                 : "=r"(b[0]), "=r"(b[1]) : "r"(addr));
}
__device__ __forceinline__ void ldmBT(uint32_t* b, uint32_t addr) {
    asm volatile("ldmatrix.sync.aligned.m8n8.x2.trans.shared.b16 {%0,%1}, [%2];"
                 : "=r"(b[0]), "=r"(b[1]) : "r"(addr));
}
__device__ __forceinline__ void mma16816(float* c, const uint32_t* a, const uint32_t* b) {
    asm volatile("mma.sync.aligned.m16n8k16.row.col.f32.f16.f16.f32 "
                 "{%0,%1,%2,%3}, {%4,%5,%6,%7}, {%8,%9}, {%0,%1,%2,%3};"
                 : "+f"(c[0]), "+f"(c[1]), "+f"(c[2]), "+f"(c[3])
                 : "r"(a[0]), "r"(a[1]), "r"(a[2]), "r"(a[3]), "r"(b[0]), "r"(b[1]));
}
__device__ __forceinline__ void cpa16(uint32_t dst, const void* src) {
    asm volatile("cp.async.cg.shared.global [%0], [%1], 16;" :: "r"(dst), "l"(src));
}
__device__ __forceinline__ void cpa_commit() {
    asm volatile("cp.async.commit_group;");
}
template<int N> __device__ __forceinline__ void cpa_wait() {
    asm volatile("cp.async.wait_group %0;" :: "n"(N));
}
__device__ __forceinline__ float ex2f(float x) {
    float y; asm("ex2.approx.f32 %0, %1;" : "=f"(y) : "f"(x)); return y;
}
__device__ __forceinline__ uint32_t packh2(float a, float b) {
    __half2 t = __floats2half2_rn(a, b);
    return *(uint32_t*)&t;
}

__global__ __launch_bounds__(256, 2)
void sdpa_stream_kernel(const float* __restrict__ Qg_,
                        const int*   __restrict__ Mg_,
                        float* __restrict__ ctx_out,
                        float* __restrict__ prob_out)
{
    extern __shared__ char smem[];
    __half* qhi_s = (__half*)(smem + OFF_Q);
    __half* qlo_s = qhi_s + 4608;
    unsigned char* maskc = (unsigned char*)(smem + OFF_MASK);
    float* rsum_s = (float*)(smem + OFF_RSUM);
    float* rinv_s = (float*)(smem + OFF_RINV);

    const int tid = threadIdx.x;
    const int w = tid >> 5, l = tid & 31;
    const int bh = blockIdx.x >> 5;
    const int qt = blockIdx.x & 31;
    const int q0 = qt * QT;
    const int b  = bh >> 4;
    const int mh = w >> 1;              // m-quarter: rows 16*mh..
    const int ns = w & 1;               // key-slice 32*ns..
    const int lr = l >> 2;
    const int lc = (l & 3) * 2;
    const int r0 = 16 * mh + lr;

    const float* Qg = Qg_ + ((size_t)bh * SS + q0) * DD;
    const int*   mg = Mg_ + (size_t)b * SS;

    // ---- init: Q split (fp16 hi/lo) into smem, mask, rowsums ----
    for (int i = tid; i < QT * DD; i += 256) {
        int r = i >> 6, d = i & 63;
        float x = Qg[i];
        __half h = __float2half_rn(x);
        qhi_s[r * 72 + d] = h;
        qlo_s[r * 72 + d] = __float2half_rn(x - __half2float(h));
    }
    for (int i = tid; i < SS; i += 256) maskc[i] = (mg[i] != 0) ? 1 : 0;
    if (tid < QT) rsum_s[tid] = 0.f;
    __syncthreads();

    // ---- Q fragments -> registers (reused across all chunks) ----
    uint32_t qh[16], ql[16];
    {
        uint32_t qb = sptr(qhi_s) + (16 * mh + (l & 15)) * 144 + (l >> 4) * 16;
#pragma unroll
        for (int kt = 0; kt < 4; kt++) {
            ldmA(qh + 4 * kt, qb + kt * 32);
            ldmA(ql + 4 * kt, qb + 9216 + kt * 32);
        }
    }

    const __half* gkh = g_kh + (size_t)bh * SS * DD;
    const __half* gkl = g_kl + (size_t)bh * SS * DD;
    const __half* gvh = g_vh + (size_t)bh * SS * DD;
    const uint32_t smem_base = sptr(smem);

    auto issue = [&](uint32_t off, int kb) {
#pragma unroll
        for (int rI = 0; rI < 6; rI++) {
            const __half* g = (rI < 2) ? gkh : (rI < 4) ? gkl : gvh;
            int rem = (rI & 1) * 256 + tid;          // 0..511
            int key = rem >> 3, seg = rem & 7;
            cpa16(smem_base + off + (rI >> 1) * ARR_B + key * 144 + seg * 16,
                  g + (size_t)(kb + key) * DD + seg * 8);
        }
        cpa_commit();
    };

    issue(OFF_BUF0, 0);

    const uint32_t kOff = (l & 7) * 144 + ((l >> 3) & 1) * 16;
    float* probRow = prob_out ? prob_out + ((size_t)bh * SS + q0 + r0) * SS : nullptr;

    float pv[8][4] = {};
    float rs0 = 0.f, rs1 = 0.f;

    for (int ch = 0; ch < NCH; ch++) {
        const uint32_t bufo = (ch & 1) ? OFF_BUF1 : OFF_BUF0;
        cpa_wait<0>();
        __syncthreads();                 // buffer visible; prior iter reads done
        if (ch + 1 < NCH)
            issue((ch & 1) ? OFF_BUF0 : OFF_BUF1, (ch + 1) * KCH);

        const uint32_t kbase = smem_base + bufo;
        const int kb = ch * KCH;
        uint32_t pah[8], pal[8];
        uint32_t bhf[2], blf[2];

        // ---- QK^T + epilogue, in two 16-key halves (register cap) ----
#pragma unroll
        for (int half = 0; half < 2; half++) {
            float accM[2][4] = {}, accL[2][4] = {};
#pragma unroll
            for (int kt = 0; kt < 4; kt++) {
#pragma unroll
                for (int t = 0; t < 2; t++) {
                    uint32_t nb = (32 * ns + 16 * half + 8 * t) * 144 + kOff + kt * 32;
                    ldmB(bhf, kbase + nb);
                    ldmB(blf, kbase + ARR_B + nb);
                    mma16816(accM[t], qh + 4 * kt, bhf);   // hh
                    mma16816(accL[t], qh + 4 * kt, blf);   // h·lo
                    mma16816(accL[t], ql + 4 * kt, bhf);   // lo·h
                }
            }
#pragma unroll
            for (int t = 0; t < 2; t++) {
                int cl = 32 * ns + 16 * half + 8 * t + lc;
                int cg = kb + cl;
                uchar2 mm = *(uchar2*)(maskc + cg);
                float p0 = mm.x ? 0.f : ex2f((accM[t][0] + accL[t][0]) * C_EXP);
                float p1 = mm.y ? 0.f : ex2f((accM[t][1] + accL[t][1]) * C_EXP);
                float p2 = mm.x ? 0.f : ex2f((accM[t][2] + accL[t][2]) * C_EXP);
                float p3 = mm.y ? 0.f : ex2f((accM[t][3] + accL[t][3]) * C_EXP);
                rs0 += p0 + p1;
                rs1 += p2 + p3;
                if (probRow) {
                    *(float2*)(probRow + cg)          = make_float2(p0, p1);
                    *(float2*)(probRow + 8 * SS + cg) = make_float2(p2, p3);
                }
                uint32_t h01 = packh2(p0, p1), h23 = packh2(p2, p3);
                pah[4 * half + 2 * t]     = h01;
                pah[4 * half + 2 * t + 1] = h23;
                __half2 b01 = *(__half2*)&h01;
                __half2 b23 = *(__half2*)&h23;
                pal[4 * half + 2 * t]     = packh2(p0 - __half2float(b01.x),
                                                   p1 - __half2float(b01.y));
                pal[4 * half + 2 * t + 1] = packh2(p2 - __half2float(b23.x),
                                                   p3 - __half2float(b23.y));
            }
        }

        // ---- PV: warp's 32-key slice x all 64 dims (two k16 groups) ----
#pragma unroll
        for (int g = 0; g < 2; g++) {
            const uint32_t vbase = kbase + 2 * ARR_B
                                 + (32 * ns + 16 * g + (l & 15)) * 144;
#pragma unroll
            for (int j = 0; j < 8; j++) {
                ldmBT(bhf, vbase + j * 16);
                mma16816(pv[j], pah + 4 * g, bhf);
                mma16816(pv[j], pal + 4 * g, bhf);
            }
        }
    }

    // ---- rowsum reduce ----
    rs0 += __shfl_xor_sync(0xffffffffu, rs0, 1);
    rs0 += __shfl_xor_sync(0xffffffffu, rs0, 2);
    rs1 += __shfl_xor_sync(0xffffffffu, rs1, 1);
    rs1 += __shfl_xor_sync(0xffffffffu, rs1, 2);
    if ((l & 3) == 0) {
        atomicAdd(&rsum_s[r0], rs0);
        atomicAdd(&rsum_s[r0 + 8], rs1);
    }
    __syncthreads();                    // (A) all PV reads + atomics done

    if (tid < QT) rinv_s[tid] = 1.0f / rsum_s[tid];

    // ---- cross-warp PV reduction: ns=1 warps write partials (reuse staging) --
    float* part = (float*)smem;         // 64 rows x 66 floats = 16896B
    if (ns == 1) {
#pragma unroll
        for (int j = 0; j < 8; j++) {
            *(float2*)(part + r0 * 66 + 8 * j + lc)       = make_float2(pv[j][0], pv[j][1]);
            *(float2*)(part + (r0 + 8) * 66 + 8 * j + lc) = make_float2(pv[j][2], pv[j][3]);
        }
    }
    __syncthreads();                    // (B)

    if (ns == 0 && ctx_out) {
        float i0 = rinv_s[r0], i1 = rinv_s[r0 + 8];
        float* c0 = ctx_out + ((size_t)bh * SS + q0 + r0) * DD;
#pragma unroll
        for (int j = 0; j < 8; j++) {
            float2 u  = *(float2*)(part + r0 * 66 + 8 * j + lc);
            float2 u2 = *(float2*)(part + (r0 + 8) * 66 + 8 * j + lc);
            *(float2*)(c0 + 8 * j + lc) =
                make_float2((pv[j][0] + u.x) * i0, (pv[j][1] + u.y) * i0);
            *(float2*)(c0 + 8 * DD + 8 * j + lc) =
                make_float2((pv[j][2] + u2.x) * i1, (pv[j][3] + u2.y) * i1);
        }
    }

    // ---- tail: normalize this block's prob rows (mostly L2-resident RMW) ----
    if (prob_out) {
        float* pbase = prob_out + ((size_t)bh * SS + q0) * SS;
#pragma unroll 4
        for (int i = tid; i < QT * (SS / 4); i += 256) {
            int row = i >> 9;
            int c = (i & 511) * 4;
            float inv = rinv_s[row];
            float4 v = *(float4*)(pbase + (size_t)row * SS + c);
            v.x *= inv; v.y *= inv; v.z *= inv; v.w *= inv;
            *(float4*)(pbase + (size_t)row * SS + c) = v;
        }
    }
}

extern "C" void kernel_launch(void* const* d_in, const int* in_sizes, int n_in,
                              void* d_out, int out_size)
{
    const float* Q = (const float*)d_in[0];
    const float* K = (const float*)d_in[1];
    const float* V = (const float*)d_in[2];
    const int*   M = (const int*)d_in[3];

    float* ctx = nullptr;
    float* prob = nullptr;
    long long os = out_size;
    if (os >= (long long)(CTX_ELEMS + PROB_ELEMS)) {
        ctx  = (float*)d_out;
        prob = (float*)d_out + CTX_ELEMS;
    } else if (os == (long long)PROB_ELEMS) {
        prob = (float*)d_out;
    } else {
        ctx  = (float*)d_out;
    }

    static bool attr_set = false;
    if (!attr_set) {
        cudaFuncSetAttribute(sdpa_stream_kernel,
                             cudaFuncAttributeMaxDynamicSharedMemorySize, SMEM_BYTES);
        attr_set = true;
    }

    prep_split_kernel<<<(NBH * SS * DD) / 256, 256>>>(K, V);
    sdpa_stream_kernel<<<NBH * (SS / QT), 256, SMEM_BYTES>>>(Q, M, ctx, prob);
}

// round 9
// speedup vs baseline: 1.2777x; 1.2777x over previous
#include <cuda_runtime.h>
#include <cuda_fp16.h>
#include <cstdint>

#define SS 2048
#define DD 64
#define NBH 32
#define QT 32
#define KCH 64
#define NCH (SS/KCH)                    // 32
#define C_EXP 0.18033688011112042f      // 0.125 * log2(e)

#define CTX_ELEMS (2LL*16*2048*64)
#define PROB_ELEMS (2LL*16*2048*2048)

// ---------------- device-global scratch (allowed) -----------------------------
__device__ __half g_kh[NBH*SS*DD];
__device__ __half g_vh[NBH*SS*DD];

__global__ void prep_split_kernel(const float* __restrict__ K,
                                  const float* __restrict__ V)
{
    int i = blockIdx.x * 256 + threadIdx.x;
    g_kh[i] = __float2half_rn(K[i]);
    g_vh[i] = __float2half_rn(V[i]);
}

// ---------------- smem layout (bytes) ----------------------------------------
// buffer: kh | vh, each 64 rows x 72 half (144B stride) = 9216
#define ARR_B   9216
#define OFF_BUF0 0
#define OFF_BUF1 18432
#define OFF_Q    36864                  // qhi 4608
#define OFF_MASK 41472                  // 2048
#define OFF_RSUM 43520                  // 32 floats (+pad)
#define OFF_RINV 43648
#define SMEM_BYTES 43776

__device__ __forceinline__ uint32_t sptr(const void* p) {
    return (uint32_t)__cvta_generic_to_shared(p);
}
__device__ __forceinline__ void ldmA(uint32_t* a, uint32_t addr) {
    asm volatile("ldmatrix.sync.aligned.m8n8.x4.shared.b16 {%0,%1,%2,%3}, [%4];"
                 : "=r"(a[0]), "=r"(a[1]), "=r"(a[2]), "=r"(a[3]) : "r"(addr));
}
__device__ __forceinline__ void ldmB4(uint32_t* b, uint32_t addr) {
    asm volatile("ldmatrix.sync.aligned.m8n8.x4.shared.b16 {%0,%1,%2,%3}, [%4];"
                 : "=r"(b[0]), "=r"(b[1]), "=r"(b[2]), "=r"(b[3]) : "r"(addr));
}
__device__ __forceinline__ void ldmBT4(uint32_t* b, uint32_t addr) {
    asm volatile("ldmatrix.sync.aligned.m8n8.x4.trans.shared.b16 {%0,%1,%2,%3}, [%4];"
                 : "=r"(b[0]), "=r"(b[1]), "=r"(b[2]), "=r"(b[3]) : "r"(addr));
}
__device__ __forceinline__ void mma16816(float* c, const uint32_t* a, const uint32_t* b) {
    asm volatile("mma.sync.aligned.m16n8k16.row.col.f32.f16.f16.f32 "
                 "{%0,%1,%2,%3}, {%4,%5,%6,%7}, {%8,%9}, {%0,%1,%2,%3};"
                 : "+f"(c[0]), "+f"(c[1]), "+f"(c[2]), "+f"(c[3])
                 : "r"(a[0]), "r"(a[1]), "r"(a[2]), "r"(a[3]), "r"(b[0]), "r"(b[1]));
}
__device__ __forceinline__ void cpa16(uint32_t dst, const void* src) {
    asm volatile("cp.async.cg.shared.global [%0], [%1], 16;" :: "r"(dst), "l"(src));
}
__device__ __forceinline__ void cpa_commit() {
    asm volatile("cp.async.commit_group;");
}
template<int N> __device__ __forceinline__ void cpa_wait() {
    asm volatile("cp.async.wait_group %0;" :: "n"(N));
}
__device__ __forceinline__ float ex2f(float x) {
    float y; asm("ex2.approx.f32 %0, %1;" : "=f"(y) : "f"(x)); return y;
}
__device__ __forceinline__ uint32_t packh2(float a, float b) {
    __half2 t = __floats2half2_rn(a, b);
    return *(uint32_t*)&t;
}

__global__ __launch_bounds__(256, 3)
void sdpa_stream_kernel(const float* __restrict__ Qg_,
                        const int*   __restrict__ Mg_,
                        float* __restrict__ ctx_out,
                        float* __restrict__ prob_out)
{
    extern __shared__ char smem[];
    __half* qhi_s = (__half*)(smem + OFF_Q);
    unsigned char* maskc = (unsigned char*)(smem + OFF_MASK);
    float* rsum_s = (float*)(smem + OFF_RSUM);
    float* rinv_s = (float*)(smem + OFF_RINV);

    const int tid = threadIdx.x;
    const int w = tid >> 5, l = tid & 31;
    const int bh = blockIdx.x >> 6;
    const int qt = blockIdx.x & 63;
    const int q0 = qt * QT;
    const int b  = bh >> 4;
    const int mh = w & 1;               // m-half: rows 16*mh..
    const int ns = w >> 1;              // key-slice 16*ns.. (0..3)
    const int lr = l >> 2;
    const int lc = (l & 3) * 2;
    const int r0 = 16 * mh + lr;

    const float* Qg = Qg_ + ((size_t)bh * SS + q0) * DD;
    const int*   mg = Mg_ + (size_t)b * SS;

    // ---- init: Q (fp16) into smem, mask, rowsums ----
    for (int i = tid; i < QT * DD; i += 256) {
        int r = i >> 6, d = i & 63;
        qhi_s[r * 72 + d] = __float2half_rn(Qg[i]);
    }
    for (int i = tid; i < SS; i += 256) maskc[i] = (mg[i] != 0) ? 1 : 0;
    if (tid < QT) rsum_s[tid] = 0.f;
    __syncthreads();

    // ---- Q fragments -> registers (reused across all chunks) ----
    uint32_t qh[16];
    {
        uint32_t qb = sptr(qhi_s) + (16 * mh + (l & 15)) * 144 + (l >> 4) * 16;
#pragma unroll
        for (int kt = 0; kt < 4; kt++) ldmA(qh + 4 * kt, qb + kt * 32);
    }

    const __half* gkh = g_kh + (size_t)bh * SS * DD;
    const __half* gvh = g_vh + (size_t)bh * SS * DD;
    const uint32_t smem_base = sptr(smem);

    auto issue = [&](uint32_t off, int kb) {
#pragma unroll
        for (int rI = 0; rI < 4; rI++) {
            const __half* g = (rI < 2) ? gkh : gvh;
            int rem = (rI & 1) * 256 + tid;          // 0..511
            int key = rem >> 3, seg = rem & 7;
            cpa16(smem_base + off + (rI >> 1) * ARR_B + key * 144 + seg * 16,
                  g + (size_t)(kb + key) * DD + seg * 8);
        }
        cpa_commit();
    };

    issue(OFF_BUF0, 0);

    // x4 B-operand addressing: lanes 0-15 -> n8 tile t=0 (k lo/hi), 16-31 -> t=1
    const uint32_t kOff4 = (16 * ns + 8 * (l >> 4) + (l & 7)) * 144
                         + ((l >> 3) & 1) * 16;
    // x4 trans V addressing: lanes 0-15 -> dim-tile jj*2, 16-31 -> jj*2+1
    const uint32_t vOff4 = (16 * ns + (l & 15)) * 144 + (l >> 4) * 16;
    float* probRow = prob_out ? prob_out + ((size_t)bh * SS + q0 + r0) * SS : nullptr;

    float pv[8][4] = {};
    float rs0 = 0.f, rs1 = 0.f;

    for (int ch = 0; ch < NCH; ch++) {
        const uint32_t bufo = (ch & 1) ? OFF_BUF1 : OFF_BUF0;
        cpa_wait<0>();
        __syncthreads();                 // buffer visible; prior iter reads done
        if (ch + 1 < NCH)
            issue((ch & 1) ? OFF_BUF0 : OFF_BUF1, (ch + 1) * KCH);

        // ---- QK^T (pure fp16): rows 16mh..+15, keys 16ns..+15 ----
        const uint32_t kbase = smem_base + bufo;
        float acc[2][4] = {};
        uint32_t bq[4];
#pragma unroll
        for (int kt = 0; kt < 4; kt++) {
            ldmB4(bq, kbase + kOff4 + kt * 32);
            mma16816(acc[0], qh + 4 * kt, bq);
            mma16816(acc[1], qh + 4 * kt, bq + 2);
        }

        // ---- epilogue: exp, mask, prob write, pack P (fp16) ----
        const int kb = ch * KCH;
        uint32_t pah[4];
#pragma unroll
        for (int t = 0; t < 2; t++) {
            int cl = 16 * ns + 8 * t + lc;
            int cg = kb + cl;
            uchar2 mm = *(uchar2*)(maskc + cg);
            float p0 = mm.x ? 0.f : ex2f(acc[t][0] * C_EXP);
            float p1 = mm.y ? 0.f : ex2f(acc[t][1] * C_EXP);
            float p2 = mm.x ? 0.f : ex2f(acc[t][2] * C_EXP);
            float p3 = mm.y ? 0.f : ex2f(acc[t][3] * C_EXP);
            rs0 += p0 + p1;
            rs1 += p2 + p3;
            if (probRow) {
                *(float2*)(probRow + cg)          = make_float2(p0, p1);
                *(float2*)(probRow + 8 * SS + cg) = make_float2(p2, p3);
            }
            pah[2 * t]     = packh2(p0, p1);
            pah[2 * t + 1] = packh2(p2, p3);
        }

        // ---- PV: warp's k16 slice x all 64 dims (x4-trans loads) ----
        const uint32_t vbase = kbase + ARR_B + vOff4;
        uint32_t bv[4];
#pragma unroll
        for (int jj = 0; jj < 4; jj++) {
            ldmBT4(bv, vbase + jj * 32);
            mma16816(pv[2 * jj],     pah, bv);
            mma16816(pv[2 * jj + 1], pah, bv + 2);
        }
    }

    // ---- rowsum reduce ----
    rs0 += __shfl_xor_sync(0xffffffffu, rs0, 1);
    rs0 += __shfl_xor_sync(0xffffffffu, rs0, 2);
    rs1 += __shfl_xor_sync(0xffffffffu, rs1, 1);
    rs1 += __shfl_xor_sync(0xffffffffu, rs1, 2);
    if ((l & 3) == 0) {
        atomicAdd(&rsum_s[r0], rs0);
        atomicAdd(&rsum_s[r0 + 8], rs1);
    }
    __syncthreads();                    // (A) all PV reads + atomics done

    if (tid < QT) rinv_s[tid] = 1.0f / rsum_s[tid];

    // ---- cross-warp PV reduction (reuse staging smem) ----
    float* part = (float*)smem;         // 96 rows x 66 floats = 25344B < 36864B
    if (ns > 0) {
        int pr = (ns - 1) * 32 + 16 * mh + lr;
#pragma unroll
        for (int j = 0; j < 8; j++) {
            *(float2*)(part + pr * 66 + 8 * j + lc)       = make_float2(pv[j][0], pv[j][1]);
            *(float2*)(part + (pr + 8) * 66 + 8 * j + lc) = make_float2(pv[j][2], pv[j][3]);
        }
    }
    __syncthreads();                    // (B)

    if (ns == 0 && ctx_out) {
#pragma unroll
        for (int j = 0; j < 8; j++) {
#pragma unroll
            for (int s = 0; s < 3; s++) {
                int pr = s * 32 + 16 * mh + lr;
                float2 u  = *(float2*)(part + pr * 66 + 8 * j + lc);
                float2 u2 = *(float2*)(part + (pr + 8) * 66 + 8 * j + lc);
                pv[j][0] += u.x;  pv[j][1] += u.y;
                pv[j][2] += u2.x; pv[j][3] += u2.y;
            }
        }
        float i0 = rinv_s[r0], i1 = rinv_s[r0 + 8];
        float* c0 = ctx_out + ((size_t)bh * SS + q0 + r0) * DD;
#pragma unroll
        for (int j = 0; j < 8; j++) {
            *(float2*)(c0 + 8 * j + lc) =
                make_float2(pv[j][0] * i0, pv[j][1] * i0);
            *(float2*)(c0 + 8 * DD + 8 * j + lc) =
                make_float2(pv[j][2] * i1, pv[j][3] * i1);
        }
    }

    // ---- tail: normalize this block's prob rows ----
    if (prob_out) {
        float* pbase = prob_out + ((size_t)bh * SS + q0) * SS;
#pragma unroll 4
        for (int i = tid; i < QT * (SS / 4); i += 256) {
            int row = i >> 9;
            int c = (i & 511) * 4;
            float inv = rinv_s[row];
            float4 v = *(float4*)(pbase + (size_t)row * SS + c);
            v.x *= inv; v.y *= inv; v.z *= inv; v.w *= inv;
            *(float4*)(pbase + (size_t)row * SS + c) = v;
        }
    }
}

extern "C" void kernel_launch(void* const* d_in, const int* in_sizes, int n_in,
                              void* d_out, int out_size)
{
    const float* Q = (const float*)d_in[0];
    const float* K = (const float*)d_in[1];
    const float* V = (const float*)d_in[2];
    const int*   M = (const int*)d_in[3];

    float* ctx = nullptr;
    float* prob = nullptr;
    long long os = out_size;
    if (os >= (long long)(CTX_ELEMS + PROB_ELEMS)) {
        ctx  = (float*)d_out;
        prob = (float*)d_out + CTX_ELEMS;
    } else if (os == (long long)PROB_ELEMS) {
        prob = (float*)d_out;
    } else {
        ctx  = (float*)d_out;
    }

    static bool attr_set = false;
    if (!attr_set) {
        cudaFuncSetAttribute(sdpa_stream_kernel,
                             cudaFuncAttributeMaxDynamicSharedMemorySize, SMEM_BYTES);
        attr_set = true;
    }

    prep_split_kernel<<<(NBH * SS * DD) / 256, 256>>>(K, V);
    sdpa_stream_kernel<<<NBH * (SS / QT), 256, SMEM_BYTES>>>(Q, M, ctx, prob);
}